// round 14
// baseline (speedup 1.0000x reference)
#include <cuda_runtime.h>
#include <cuda_fp16.h>
#include <cstdint>

#define BB   8
#define LSEQ 4096
#define CDIM 256
#define DI   512
#define E2   1024
#define NTOK (BB*LSEQ)
#define CH   128
#define NCH  32

// fp32 scratch
__device__ float g_xz  [(size_t)NTOK*E2];
__device__ float g_xcf [NTOK*DI];
__device__ float g_xcr [NTOK*DI];
__device__ float g_dblf[NTOK*48];
__device__ float g_dblr[NTOK*48];
__device__ float g_yf  [NTOK*DI];
__device__ float g_yr  [NTOK*DI];
__device__ float g_mo  [NTOK*CDIM];
__device__ float g_hout[2*8*NCH*16*DI];
__device__ float g_hin [2*8*NCH*16*DI];
__device__ float g_S   [2*8*NCH*DI];
// fp16 split planes: activations hi+lo, weights hi only
__device__ __half g_xnh [NTOK*CDIM],  g_xnl [NTOK*CDIM];
__device__ __half g_xcfh[NTOK*DI],    g_xcfl[NTOK*DI];
__device__ __half g_xcrh[NTOK*DI],    g_xcrl[NTOK*DI];
__device__ __half g_ysh [NTOK*DI],    g_ysl [NTOK*DI];
__device__ __half g_xmnh[NTOK*CDIM],  g_xmnl[NTOK*CDIM];
__device__ __half g_inwh[E2*CDIM];
__device__ __half g_owh [CDIM*DI];
__device__ __half g_pwh [CDIM*CDIM];
__device__ __half g_xpfh[48*DI];
__device__ __half g_xprh[48*DI];

// ================= fp16 mma.sync GEMM over virtual K' = 2K =================
// C[m,n] = Ah·Bh + Al·Bh   (fp16 planes, fp32 accumulate)
// Block 128x64, BK=32, 256 threads = 8 warps (4x2), warp tile 32x32.
// cp.async 2-stage double buffer.
#define SAS 40   // smem row stride in fp16 elems (80B) — conflict-free frag loads

__device__ __forceinline__ void mma16816(float* d, const uint32_t* a, const uint32_t* b) {
    asm volatile(
        "mma.sync.aligned.m16n8k16.row.col.f32.f16.f16.f32 "
        "{%0,%1,%2,%3}, {%4,%5,%6,%7}, {%8,%9}, {%0,%1,%2,%3};"
        : "+f"(d[0]), "+f"(d[1]), "+f"(d[2]), "+f"(d[3])
        : "r"(a[0]), "r"(a[1]), "r"(a[2]), "r"(a[3]), "r"(b[0]), "r"(b[1]));
}
__device__ __forceinline__ void cp16(uint32_t dst, const void* src, uint32_t sz) {
    asm volatile("cp.async.ca.shared.global [%0], [%1], 16, %2;"
                 :: "r"(dst), "l"(src), "r"(sz));
}

template<bool HAS_BIAS, bool TRANS_OUT>
__global__ void __launch_bounds__(256)
gemm_mma(int K, const __half* __restrict__ Ah, const __half* __restrict__ Al,
         const __half* __restrict__ Bh,
         float* __restrict__ C, int ldc, int Nact, const float* __restrict__ bias)
{
    __shared__ __align__(16) __half As[2][128*SAS];
    __shared__ __align__(16) __half Bs[2][64*SAS];

    int tid = threadIdx.x;
    int m0 = blockIdx.x * 128, n0 = blockIdx.y * 64;

    // loader indices
    int lrow  = tid >> 1;             // A row 0..127
    int lhalf = (tid & 1) << 4;       // 0 | 16 elems
    int brow  = tid >> 2;             // B row 0..63
    int bseg  = (tid & 3) << 3;       // 0,8,16,24 elems
    bool bok  = (n0 + brow) < Nact;

    uint32_t sA[2], sB[2];
    #pragma unroll
    for (int s = 0; s < 2; s++) {
        sA[s] = (uint32_t)__cvta_generic_to_shared(&As[s][lrow*SAS + lhalf]);
        sB[s] = (uint32_t)__cvta_generic_to_shared(&Bs[s][brow*SAS + bseg]);
    }
    size_t aoff = (size_t)(m0 + lrow)*K + lhalf;
    size_t boff = bok ? ((size_t)(n0 + brow)*K + bseg) : 0;
    uint32_t bsz = bok ? 16u : 0u;

    // warp/frag indices
    int wid = tid >> 5, lane = tid & 31;
    int wm = (wid & 3) << 5;
    int wn = (wid >> 2) << 5;
    int r4 = lane >> 2, c2 = (lane & 3) << 1;

    float acc[2][4][4];
    #pragma unroll
    for (int i = 0; i < 2; i++)
        #pragma unroll
        for (int j = 0; j < 4; j++)
            #pragma unroll
            for (int q = 0; q < 4; q++) acc[i][j][q] = 0.f;

    int niter = (2*K) >> 5;

    // prologue: issue loads for iter 0
    {
        const __half* Ap = Ah + aoff;
        cp16(sA[0], Ap, 16);
        cp16(sA[0] + 16, Ap + 8, 16);
        cp16(sB[0], Bh + boff, bsz);
        asm volatile("cp.async.commit_group;");
    }

    for (int it = 0; it < niter; it++) {
        int stage = it & 1;
        if (it + 1 < niter) {
            int ks = (it + 1) << 5;
            int seg = (ks >= K) ? 1 : 0;
            int kk = ks - seg*K;
            const __half* Ap = (seg ? Al : Ah) + aoff + kk;
            int ns = (it + 1) & 1;
            cp16(sA[ns], Ap, 16);
            cp16(sA[ns] + 16, Ap + 8, 16);
            cp16(sB[ns], Bh + boff + kk, bsz);
            asm volatile("cp.async.commit_group;");
            asm volatile("cp.async.wait_group 1;");
        } else {
            asm volatile("cp.async.wait_group 0;");
        }
        __syncthreads();

        #pragma unroll
        for (int k16 = 0; k16 < 32; k16 += 16) {
            uint32_t af[2][4];
            #pragma unroll
            for (int im = 0; im < 2; im++) {
                int base = (wm + im*16 + r4)*SAS + k16 + c2;
                af[im][0] = *(const uint32_t*)&As[stage][base];
                af[im][1] = *(const uint32_t*)&As[stage][base + 8*SAS];
                af[im][2] = *(const uint32_t*)&As[stage][base + 8];
                af[im][3] = *(const uint32_t*)&As[stage][base + 8*SAS + 8];
            }
            uint32_t bf[4][2];
            #pragma unroll
            for (int jn = 0; jn < 4; jn++) {
                int base = (wn + jn*8 + r4)*SAS + k16 + c2;
                bf[jn][0] = *(const uint32_t*)&Bs[stage][base];
                bf[jn][1] = *(const uint32_t*)&Bs[stage][base + 8];
            }
            #pragma unroll
            for (int im = 0; im < 2; im++)
                #pragma unroll
                for (int jn = 0; jn < 4; jn++)
                    mma16816(acc[im][jn], af[im], bf[jn]);
        }
        __syncthreads();
    }

    // epilogue
    #pragma unroll
    for (int im = 0; im < 2; im++) {
        int r = m0 + wm + im*16 + r4;
        #pragma unroll
        for (int jn = 0; jn < 4; jn++) {
            int gc = n0 + wn + jn*8 + c2;
            if (gc < Nact) {
                float b0 = HAS_BIAS ? bias[gc]   : 0.f;
                float b1 = HAS_BIAS ? bias[gc+1] : 0.f;
                if (!TRANS_OUT) {
                    C[(size_t)r*ldc + gc]       = acc[im][jn][0] + b0;
                    C[(size_t)r*ldc + gc + 1]   = acc[im][jn][1] + b1;
                    C[(size_t)(r+8)*ldc + gc]   = acc[im][jn][2] + b0;
                    C[(size_t)(r+8)*ldc + gc+1] = acc[im][jn][3] + b1;
                } else {
                    int bo0 = r >> 12, l0 = r & 4095;
                    int t1 = r + 8;
                    int bo1 = t1 >> 12, l1 = t1 & 4095;
                    C[((size_t)bo0*ldc + gc)*LSEQ + l0]     = acc[im][jn][0] + b0;
                    C[((size_t)bo0*ldc + gc + 1)*LSEQ + l0] = acc[im][jn][1] + b1;
                    C[((size_t)bo1*ldc + gc)*LSEQ + l1]     = acc[im][jn][2] + b0;
                    C[((size_t)bo1*ldc + gc + 1)*LSEQ + l1] = acc[im][jn][3] + b1;
                }
            }
        }
    }
}

// ================= weight convert (all 5 in one launch) =================
__global__ void wcvt(const float* __restrict__ a, const float* __restrict__ b,
                     const float* __restrict__ c, const float* __restrict__ d,
                     const float* __restrict__ e,
                     __half* oa, __half* ob, __half* oc, __half* od, __half* oe)
{
    int i = blockIdx.x*256 + threadIdx.x;
    if (i < E2*CDIM)   oa[i] = __float2half(a[i]);
    if (i < CDIM*DI)   ob[i] = __float2half(b[i]);
    if (i < CDIM*CDIM) oc[i] = __float2half(c[i]);
    if (i < 48*DI) { od[i] = __float2half(d[i]); oe[i] = __float2half(e[i]); }
}

__global__ void ysum_split(const float* __restrict__ a, const float* __restrict__ b,
                           __half* __restrict__ h, __half* __restrict__ lo)
{
    int i = blockIdx.x*256 + threadIdx.x;
    float v = a[i] + b[i];
    __half hb = __float2half(v);
    h[i] = hb;
    lo[i] = __float2half(v - __half2float(hb));
}

// ---- LayerNorm over c of x[b,c,l] (+optional mo + skip) -> fp16 hi/lo [b,l,c] ----
template<bool ADD_MO>
__global__ void ln_kernel(const float* __restrict__ x,
                          const float* __restrict__ g,
                          const float* __restrict__ be,
                          const float* __restrict__ skip,
                          __half* __restrict__ oh,
                          __half* __restrict__ ol)
{
    __shared__ float sm[256][33];
    __shared__ float smean[32], srstd[32];
    int l0 = blockIdx.x * 32, b = blockIdx.y, tid = threadIdx.x;
    const float* xb = x + (size_t)b*CDIM*LSEQ;
    #pragma unroll
    for (int i = 0; i < 32; i++) {
        int idx = tid + i*256, c = idx >> 5, li = idx & 31;
        sm[c][li] = xb[(size_t)c*LSEQ + l0 + li];
    }
    __syncthreads();
    float sk = ADD_MO ? skip[0] : 0.f;
    const float* mo = g_mo + ((size_t)b*LSEQ + l0)*CDIM;
    int w = tid >> 5, lane = tid & 31;
    for (int li = w; li < 32; li += 8) {
        float s = 0.f, s2 = 0.f;
        #pragma unroll
        for (int j = 0; j < 8; j++) {
            int c = lane + (j << 5);
            float v = sm[c][li];
            if (ADD_MO) { v = fmaf(sk, v, mo[(size_t)li*CDIM + c]); sm[c][li] = v; }
            s += v; s2 += v*v;
        }
        #pragma unroll
        for (int off = 16; off; off >>= 1) {
            s  += __shfl_xor_sync(0xffffffffu, s,  off);
            s2 += __shfl_xor_sync(0xffffffffu, s2, off);
        }
        if (lane == 0) {
            float m = s * (1.f/256.f);
            smean[li] = m;
            srstd[li] = rsqrtf(s2*(1.f/256.f) - m*m + 1e-5f);
        }
    }
    __syncthreads();
    size_t base = ((size_t)b*LSEQ + l0)*CDIM;
    #pragma unroll
    for (int i = 0; i < 32; i++) {
        int idx = tid + i*256, li = idx >> 8, c = idx & 255;
        float v = (sm[c][li] - smean[li])*srstd[li]*g[c] + be[c];
        __half hb = __float2half(v);
        oh[base + (size_t)li*CDIM + c] = hb;
        ol[base + (size_t)li*CDIM + c] = __float2half(v - __half2float(hb));
    }
}

// ---- causal depthwise conv + SiLU; writes fp32 (scan) + fp16 hi/lo (GEMM) ----
__global__ void conv_kernel(const float* __restrict__ cwf, const float* __restrict__ cbf,
                            const float* __restrict__ cwr, const float* __restrict__ cbr)
{
    int idx = blockIdx.x*256 + threadIdx.x;
    int d = idx & (DI-1), l = (idx >> 9) & (LSEQ-1), b = (idx >> 21) & 7, dir = idx >> 24;
    const float* w = (dir ? cwr : cwf) + d*4;
    float acc = (dir ? cbr : cbf)[d];
    const float* xzb = g_xz + (size_t)b*LSEQ*E2 + d;
    #pragma unroll
    for (int j = 0; j < 4; j++) {
        int ir = l - 3 + j;
        if (ir >= 0) {
            int ls = dir ? (LSEQ-1-ir) : ir;
            acc = fmaf(w[j], xzb[(size_t)ls*E2], acc);
        }
    }
    float s = __fdividef(acc, 1.f + __expf(-acc));
    size_t o = ((size_t)b*LSEQ + l)*DI + d;
    __half hb = __float2half(s);
    __half lb = __float2half(s - __half2float(hb));
    if (dir) { g_xcr[o] = s; g_xcrh[o] = hb; g_xcrl[o] = lb; }
    else     { g_xcf[o] = s; g_xcfh[o] = hb; g_xcfl[o] = lb; }
}

// ================= chunk-parallel selective scan =================
__global__ void __launch_bounds__(256)
scan_p1(const float* __restrict__ dtw_f, const float* __restrict__ dtb_f,
        const float* __restrict__ alog_f,
        const float* __restrict__ dtw_r, const float* __restrict__ dtb_r,
        const float* __restrict__ alog_r)
{
    int tid = threadIdx.x;
    int chunk = blockIdx.x >> 1;
    int d = ((blockIdx.x & 1) << 8) | tid;
    int b = blockIdx.y, dir = blockIdx.z;

    const float* dbl = dir ? g_dblr : g_dblf;
    const float* xc  = dir ? g_xcr  : g_xcf;
    const float* dtw = (dir ? dtw_r : dtw_f) + d*16;
    const float* alg = (dir ? alog_r : alog_f) + d*16;
    float dtb = (dir ? dtb_r : dtb_f)[d];

    float W[16], A[16], h[16];
    bool fast = true;
    #pragma unroll
    for (int n = 0; n < 16; n++) {
        W[n] = dtw[n];
        A[n] = -__expf(alg[n]);
        h[n] = 0.f;
        fast = fast && (fabsf(-A[n] - (float)(n+1)) < 1e-4f*(float)(n+1));
    }

    size_t t0 = (size_t)b*LSEQ + (size_t)chunk*CH;
    const float4* dq = (const float4*)dbl + t0*12;
    const float*  xcp = xc + t0*DI + d;
    float S = 0.f;

    if (fast) {
        for (int l = 0; l < CH; l++) {
            float q[32];
            #pragma unroll
            for (int i = 0; i < 8; i++) ((float4*)q)[i] = dq[(size_t)l*12 + i];
            float xv = xcp[(size_t)l*DI];
            float a0 = dtb, a1 = 0.f, a2 = 0.f, a3 = 0.f;
            #pragma unroll
            for (int k = 0; k < 16; k += 4) {
                a0 = fmaf(q[k+0], W[k+0], a0); a1 = fmaf(q[k+1], W[k+1], a1);
                a2 = fmaf(q[k+2], W[k+2], a2); a3 = fmaf(q[k+3], W[k+3], a3);
            }
            float dt = (a0+a1)+(a2+a3);
            float ed = __expf(dt);
            float sp = (dt > 15.f) ? dt : __logf(1.f + ed);
            S += sp;
            float dtx = sp * xv;
            float pw[16];
            pw[0] = __fdividef(1.f, 1.f + ed);
            #pragma unroll
            for (int n = 1; n < 16; n++) pw[n] = pw[n>>1] * pw[(n-1)>>1];
            #pragma unroll
            for (int n = 0; n < 16; n++) h[n] = fmaf(pw[n], h[n], dtx*q[16+n]);
        }
    } else {
        for (int l = 0; l < CH; l++) {
            float q[32];
            #pragma unroll
            for (int i = 0; i < 8; i++) ((float4*)q)[i] = dq[(size_t)l*12 + i];
            float xv = xcp[(size_t)l*DI];
            float a0 = dtb, a1 = 0.f, a2 = 0.f, a3 = 0.f;
            #pragma unroll
            for (int k = 0; k < 16; k += 4) {
                a0 = fmaf(q[k+0], W[k+0], a0); a1 = fmaf(q[k+1], W[k+1], a1);
                a2 = fmaf(q[k+2], W[k+2], a2); a3 = fmaf(q[k+3], W[k+3], a3);
            }
            float dt = (a0+a1)+(a2+a3);
            float ed = __expf(dt);
            float sp = (dt > 15.f) ? dt : __logf(1.f + ed);
            S += sp;
            float dtx = sp * xv;
            #pragma unroll
            for (int n = 0; n < 16; n++)
                h[n] = fmaf(__expf(sp*A[n]), h[n], dtx*q[16+n]);
        }
    }
    size_t base = (size_t)((dir*8 + b)*NCH + chunk);
    #pragma unroll
    for (int n = 0; n < 16; n++) g_hout[(base*16 + n)*DI + d] = h[n];
    g_S[base*DI + d] = S;
}

__global__ void __launch_bounds__(256)
scan_p2(const float* __restrict__ alog_f, const float* __restrict__ alog_r)
{
    int t = blockIdx.x*256 + threadIdx.x;
    int dir = t >> 12, b = (t >> 9) & 7, d = t & 511;
    const float* alg = (dir ? alog_r : alog_f) + d*16;
    float A[16], H[16];
    bool fast = true;
    #pragma unroll
    for (int n = 0; n < 16; n++) {
        A[n] = -__expf(alg[n]);
        H[n] = 0.f;
        fast = fast && (fabsf(-A[n] - (float)(n+1)) < 1e-4f*(float)(n+1));
    }
    size_t dirb = (size_t)(dir*8 + b);
    for (int c = 0; c < NCH; c++) {
        size_t base = dirb*NCH + c;
        #pragma unroll
        for (int n = 0; n < 16; n++) g_hin[(base*16 + n)*DI + d] = H[n];
        float S = g_S[base*DI + d];
        if (fast) {
            float pw[16];
            pw[0] = __expf(-S);
            #pragma unroll
            for (int n = 1; n < 16; n++) pw[n] = pw[n>>1] * pw[(n-1)>>1];
            #pragma unroll
            for (int n = 0; n < 16; n++)
                H[n] = fmaf(pw[n], H[n], g_hout[(base*16 + n)*DI + d]);
        } else {
            #pragma unroll
            for (int n = 0; n < 16; n++)
                H[n] = fmaf(__expf(A[n]*S), H[n], g_hout[(base*16 + n)*DI + d]);
        }
    }
}

__global__ void __launch_bounds__(256)
scan_p3(const float* __restrict__ dtw_f, const float* __restrict__ dtb_f,
        const float* __restrict__ alog_f, const float* __restrict__ dp_f,
        const float* __restrict__ dtw_r, const float* __restrict__ dtb_r,
        const float* __restrict__ alog_r, const float* __restrict__ dp_r)
{
    int tid = threadIdx.x;
    int chunk = blockIdx.x >> 1;
    int d = ((blockIdx.x & 1) << 8) | tid;
    int b = blockIdx.y, dir = blockIdx.z;

    const float* dbl = dir ? g_dblr : g_dblf;
    const float* xc  = dir ? g_xcr  : g_xcf;
    const float* dtw = (dir ? dtw_r : dtw_f) + d*16;
    const float* alg = (dir ? alog_r : alog_f) + d*16;
    float dtb = (dir ? dtb_r : dtb_f)[d];
    float Dpv = (dir ? dp_r  : dp_f )[d];

    float W[16], A[16], h[16];
    bool fast = true;
    size_t base = (size_t)((dir*8 + b)*NCH + chunk);
    #pragma unroll
    for (int n = 0; n < 16; n++) {
        W[n] = dtw[n];
        A[n] = -__expf(alg[n]);
        h[n] = g_hin[(base*16 + n)*DI + d];
        fast = fast && (fabsf(-A[n] - (float)(n+1)) < 1e-4f*(float)(n+1));
    }

    size_t t0 = (size_t)b*LSEQ + (size_t)chunk*CH;
    const float4* dq = (const float4*)dbl + t0*12;
    const float*  xcp = xc + t0*DI + d;
    const float*  zb  = g_xz + (size_t)b*LSEQ*E2 + DI + d;
    float* yp = (dir ? g_yr : g_yf) + (size_t)b*LSEQ*DI + d;

    for (int l = 0; l < CH; l++) {
        float q[48];
        #pragma unroll
        for (int i = 0; i < 12; i++) ((float4*)q)[i] = dq[(size_t)l*12 + i];
        float xv = xcp[(size_t)l*DI];
        int lf = chunk*CH + l;
        int zl = dir ? (LSEQ-1-lf) : lf;
        float zv = zb[(size_t)zl*E2];

        float a0 = dtb, a1 = 0.f, a2 = 0.f, a3 = 0.f;
        #pragma unroll
        for (int k = 0; k < 16; k += 4) {
            a0 = fmaf(q[k+0], W[k+0], a0); a1 = fmaf(q[k+1], W[k+1], a1);
            a2 = fmaf(q[k+2], W[k+2], a2); a3 = fmaf(q[k+3], W[k+3], a3);
        }
        float dt = (a0+a1)+(a2+a3);
        float ed = __expf(dt);
        float sp = (dt > 15.f) ? dt : __logf(1.f + ed);
        float dtx = sp * xv;
        float y0 = 0.f, y1 = 0.f, y2 = 0.f, y3 = 0.f;
        if (fast) {
            float pw[16];
            pw[0] = __fdividef(1.f, 1.f + ed);
            #pragma unroll
            for (int n = 1; n < 16; n++) pw[n] = pw[n>>1] * pw[(n-1)>>1];
            #pragma unroll
            for (int n = 0; n < 16; n += 4) {
                h[n+0] = fmaf(pw[n+0], h[n+0], dtx*q[16+n+0]); y0 = fmaf(h[n+0], q[32+n+0], y0);
                h[n+1] = fmaf(pw[n+1], h[n+1], dtx*q[16+n+1]); y1 = fmaf(h[n+1], q[32+n+1], y1);
                h[n+2] = fmaf(pw[n+2], h[n+2], dtx*q[16+n+2]); y2 = fmaf(h[n+2], q[32+n+2], y2);
                h[n+3] = fmaf(pw[n+3], h[n+3], dtx*q[16+n+3]); y3 = fmaf(h[n+3], q[32+n+3], y3);
            }
        } else {
            #pragma unroll
            for (int n = 0; n < 16; n++) {
                h[n] = fmaf(__expf(sp*A[n]), h[n], dtx*q[16+n]);
                y0 = fmaf(h[n], q[32+n], y0);
            }
        }
        float y = (y0+y1)+(y2+y3);
        float sz = __fdividef(zv, 1.f + __expf(-zv));
        int sl = dir ? (LSEQ-1-lf) : lf;
        yp[(size_t)sl*DI] = fmaf(Dpv, xv, y) * sz;
    }
}

// ================= launch =================
extern "C" void kernel_launch(void* const* d_in, const int* in_sizes, int n_in,
                              void* d_out, int out_size)
{
    const float* x       = (const float*)d_in[0];
    const float* norm_g  = (const float*)d_in[1];
    const float* norm_b  = (const float*)d_in[2];
    const float* skip    = (const float*)d_in[3];
    const float* proj_w  = (const float*)d_in[4];
    const float* proj_b  = (const float*)d_in[5];
    const float* in_w    = (const float*)d_in[6];
    const float* out_w   = (const float*)d_in[7];
    const float* cwf     = (const float*)d_in[8];
    const float* cbf     = (const float*)d_in[9];
    const float* xpw_f   = (const float*)d_in[10];
    const float* dtw_f   = (const float*)d_in[11];
    const float* dtb_f   = (const float*)d_in[12];
    const float* alog_f  = (const float*)d_in[13];
    const float* dp_f    = (const float*)d_in[14];
    const float* cwr     = (const float*)d_in[15];
    const float* cbr     = (const float*)d_in[16];
    const float* xpw_r   = (const float*)d_in[17];
    const float* dtw_r   = (const float*)d_in[18];
    const float* dtb_r   = (const float*)d_in[19];
    const float* alog_r  = (const float*)d_in[20];
    const float* dp_r    = (const float*)d_in[21];
    float* out = (float*)d_out;

    #define SYM(p, s) float* p; cudaGetSymbolAddress((void**)&p, s)
    #define SYMH(p, s) __half* p; cudaGetSymbolAddress((void**)&p, s)
    SYM(p_xz, g_xz); SYM(p_dblf, g_dblf); SYM(p_dblr, g_dblr);
    SYM(p_yf, g_yf); SYM(p_yr, g_yr); SYM(p_mo, g_mo);
    SYMH(p_xnh, g_xnh);  SYMH(p_xnl, g_xnl);
    SYMH(p_xcfh, g_xcfh); SYMH(p_xcfl, g_xcfl);
    SYMH(p_xcrh, g_xcrh); SYMH(p_xcrl, g_xcrl);
    SYMH(p_ysh, g_ysh);  SYMH(p_ysl, g_ysl);
    SYMH(p_xmnh, g_xmnh); SYMH(p_xmnl, g_xmnl);
    SYMH(p_inwh, g_inwh);
    SYMH(p_owh, g_owh);
    SYMH(p_pwh, g_pwh);
    SYMH(p_xpfh, g_xpfh);
    SYMH(p_xprh, g_xprh);

    wcvt<<<(E2*CDIM+255)/256, 256>>>(in_w, out_w, proj_w, xpw_f, xpw_r,
                                     p_inwh, p_owh, p_pwh, p_xpfh, p_xprh);

    dim3 lng(LSEQ/32, BB);
    ln_kernel<false><<<lng, 256>>>(x, norm_g, norm_b, skip, p_xnh, p_xnl);

    gemm_mma<false,false><<<dim3(NTOK/128, E2/64), 256>>>(
        CDIM, p_xnh, p_xnl, p_inwh, p_xz, E2, E2, nullptr);

    conv_kernel<<<(2*NTOK*DI)/256, 256>>>(cwf, cbf, cwr, cbr);

    gemm_mma<false,false><<<dim3(NTOK/128, 1), 256>>>(
        DI, p_xcfh, p_xcfl, p_xpfh, p_dblf, 48, 48, nullptr);
    gemm_mma<false,false><<<dim3(NTOK/128, 1), 256>>>(
        DI, p_xcrh, p_xcrl, p_xprh, p_dblr, 48, 48, nullptr);

    dim3 sg(2*NCH, BB, 2);
    scan_p1<<<sg, 256>>>(dtw_f, dtb_f, alog_f, dtw_r, dtb_r, alog_r);
    scan_p2<<<32, 256>>>(alog_f, alog_r);
    scan_p3<<<sg, 256>>>(dtw_f, dtb_f, alog_f, dp_f, dtw_r, dtb_r, alog_r, dp_r);

    ysum_split<<<(NTOK*DI)/256, 256>>>(p_yf, p_yr, p_ysh, p_ysl);

    gemm_mma<false,false><<<dim3(NTOK/128, CDIM/64), 256>>>(
        DI, p_ysh, p_ysl, p_owh, p_mo, CDIM, CDIM, nullptr);

    ln_kernel<true><<<lng, 256>>>(x, norm_g, norm_b, skip, p_xmnh, p_xmnl);

    gemm_mma<true,true><<<dim3(NTOK/128, CDIM/64), 256>>>(
        CDIM, p_xmnh, p_xmnl, p_pwh, out, CDIM, CDIM, proj_b);
}